// round 14
// baseline (speedup 1.0000x reference)
#include <cuda_runtime.h>
#include <cuda_fp16.h>
#include <math.h>
#include <stdint.h>

// ============================================================================
// Problem constants
// ============================================================================
#define B_  4096
#define IN_ 512
#define H_  1024
#define O_  256
#define L_  2
#define G_  3
#define NH  (G_ * O_)        // 768 per head
#define NHEADS3 (3 * NH)     // 2304 fused head columns

// ============================================================================
// GEMM tiling: 128x128 block, 4 warps (128 thr), 64x64 warp tile, BK=64
// ============================================================================
#define BM 128
#define BN 128
#define BK 64
#define PH 72                           // smem pitch in halves (144 B rows)
#define ATB (BM * PH * 2)               // 18432 B per operand tile
#define STG_BYTES (2 * ATB)             // 36864 (A + W per stage)
#define NSTG 3
#define SMEM_BYTES (NSTG * STG_BYTES)   // 110592

// ============================================================================
// Scratch (device globals)
// ============================================================================
static __device__ __align__(256) __half g_xh    [(size_t)B_ * IN_];
static __device__ __align__(256) __half g_hidh  [(size_t)L_ * B_ * H_];
static __device__ __align__(256) __half g_i2dwh [(size_t)H_ * IN_];
static __device__ __align__(256) __half g_wihh  [(size_t)L_ * 3 * H_ * H_];
static __device__ __align__(256) __half g_whhh  [(size_t)L_ * 3 * H_ * H_];
static __device__ __align__(256) __half g_headwh[(size_t)NHEADS3 * H_];
static __device__ __align__(256) __half g_h1h   [(size_t)B_ * H_];
static __device__ __align__(256) __half g_gih   [(size_t)B_ * 3 * H_];
static __device__ __align__(256) __half g_ghh   [(size_t)B_ * 3 * H_];
static __device__ __align__(256) __half g_h2h   [(size_t)B_ * H_];
static __device__ __align__(256) __half g_houth [(size_t)B_ * H_];

// ============================================================================
// PTX helpers
// ============================================================================
__device__ __forceinline__ void gdc_wait() {
    asm volatile("griddepcontrol.wait;" ::: "memory");
}
__device__ __forceinline__ void gdc_launch() {
    asm volatile("griddepcontrol.launch_dependents;" ::: "memory");
}

__device__ __forceinline__ void cp_async16(uint32_t saddr, const void* gptr) {
    asm volatile("cp.async.cg.shared.global [%0], [%1], 16;"
                 :: "r"(saddr), "l"(gptr) : "memory");
}
__device__ __forceinline__ void cp_commit() {
    asm volatile("cp.async.commit_group;" ::: "memory");
}
__device__ __forceinline__ void cp_wait2() {
    asm volatile("cp.async.wait_group 2;" ::: "memory");
}
__device__ __forceinline__ void cp_wait1() {
    asm volatile("cp.async.wait_group 1;" ::: "memory");
}
__device__ __forceinline__ void cp_wait0() {
    asm volatile("cp.async.wait_group 0;" ::: "memory");
}

#define LDSM4(r, a) \
    asm volatile("ldmatrix.sync.aligned.m8n8.x4.shared.b16 {%0,%1,%2,%3}, [%4];" \
        : "=r"((r)[0]), "=r"((r)[1]), "=r"((r)[2]), "=r"((r)[3]) : "r"(a))

__device__ __forceinline__ void mma_f16(float c[4], const uint32_t a[4],
                                        uint32_t b0, uint32_t b1) {
    asm volatile(
        "mma.sync.aligned.m16n8k16.row.col.f32.f16.f16.f32 "
        "{%0,%1,%2,%3}, {%4,%5,%6,%7}, {%8,%9}, {%0,%1,%2,%3};"
        : "+f"(c[0]), "+f"(c[1]), "+f"(c[2]), "+f"(c[3])
        : "r"(a[0]), "r"(a[1]), "r"(a[2]), "r"(a[3]), "r"(b0), "r"(b1));
}

__device__ __forceinline__ float tanha(float x) {
    float y;
    asm("tanh.approx.f32 %0, %1;" : "=f"(y) : "f"(x));
    return y;
}
__device__ __forceinline__ float sigma_f(float x) {
    return fmaf(0.5f, tanha(0.5f * x), 0.5f);
}

// ============================================================================
// Per-launch segment table
// ============================================================================
struct Seg {
    const __half* A;
    const __half* W;
    const float*  b0;
    const float*  b1;
    const float*  b2;
    float*        Cf;
    __half*       Ch;
    int           act;     // 0 half out, 1 relu->half, 2 heads f32 (softplus seg1)
};
struct GemmP {
    Seg s[2];
    int xTiles;
    int N;
    int K;
    int segN;
};

// ============================================================================
// GEMM: 128 threads, 4 warps in 2x2 grid, 64x64 per warp.
// ============================================================================
__global__ __launch_bounds__(128, 2)
void gemm_f16(const __grid_constant__ GemmP p)
{
    extern __shared__ char smem_raw[];
    const uint32_t sbase = (uint32_t)__cvta_generic_to_shared(smem_raw);

    const int tid  = threadIdx.x;
    const int lane = tid & 31;
    const int wid  = tid >> 5;       // 0..3
    const int wm   = wid & 1;        // 2 warps along M (64 rows)
    const int wn   = wid >> 1;       // 2 warps along N (64 cols)

    const int segi = (blockIdx.x >= p.xTiles) ? 1 : 0;
    const int bn   = (blockIdx.x - segi * p.xTiles) * BN;
    const int bm   = blockIdx.y * BM;
    const Seg sg   = p.s[segi];
    const int K    = p.K;
    const int N    = p.N;

    float acc[4][8][4];
#pragma unroll
    for (int i = 0; i < 4; ++i)
#pragma unroll
        for (int j = 0; j < 8; ++j)
#pragma unroll
            for (int q = 0; q < 4; ++q) acc[i][j][q] = 0.f;

    const __half* __restrict__ Ap = sg.A;
    const __half* __restrict__ Wp = sg.W;
    // 128 threads: 8 x 16B chunks per thread for A and for W per stage
    auto issue = [&](int stg, int kt) {
        uint32_t sa = sbase + stg * STG_BYTES;
        uint32_t sb = sa + ATB;
#pragma unroll
        for (int i = 0; i < 8; ++i) {
            int idx = tid + i * 128;
            int row = idx >> 3;
            int c8  = (idx & 7) << 3;
            uint32_t doff = (uint32_t)(row * PH + c8) * 2;
            cp_async16(sa + doff, Ap + (size_t)(bm + row) * K + kt + c8);
            cp_async16(sb + doff, Wp + (size_t)(bn + row) * K + kt + c8);
        }
        cp_commit();
    };

    gdc_wait();

    const int nT = K / BK;
    issue(0, 0);
    issue(1, BK);
    issue(2, 2 * BK);

    // ldmatrix lane addressing (pitch PH halves)
    const uint32_t aOff = (uint32_t)(((wm * 64 + (lane & 15)) * PH +
                                      ((lane >> 4) << 3)) * 2);
    const uint32_t bOff = (uint32_t)(((wn * 64 + ((lane >> 4) << 3) + (lane & 7)) * PH +
                                      (((lane >> 3) & 1) << 3)) * 2);

    uint32_t afb[2][4][4];
    uint32_t bfb[2][4][4];   // 4 pair-groups of 16 B-rows each (64 cols)

    auto ldsm_half = [&](int s, int kk, int bsel) {
        uint32_t sa = sbase + s * STG_BYTES;
        uint32_t sb = sa + ATB;
#pragma unroll
        for (int mt = 0; mt < 4; ++mt)
            LDSM4(afb[bsel][mt], sa + aOff + (uint32_t)(mt * 16 * PH + kk) * 2);
#pragma unroll
        for (int pq = 0; pq < 4; ++pq)
            LDSM4(bfb[bsel][pq], sb + bOff + (uint32_t)(pq * 16 * PH + kk) * 2);
    };
    auto mma_half = [&](int b) {
#pragma unroll
        for (int mt = 0; mt < 4; ++mt)
#pragma unroll
            for (int nt = 0; nt < 8; ++nt)
                mma_f16(acc[mt][nt], afb[b][mt],
                        bfb[b][nt >> 1][(nt & 1) * 2],
                        bfb[b][nt >> 1][(nt & 1) * 2 + 1]);
    };

    cp_wait2();
    __syncthreads();
    ldsm_half(0, 0, 0);

    for (int t = 0; t < nT; ++t) {
        const int s = t % NSTG;
        ldsm_half(s, 16, 1);
        mma_half(0);
        ldsm_half(s, 32, 0);
        mma_half(1);
        ldsm_half(s, 48, 1);
        mma_half(0);
        if (t + 1 < nT) {
            if (t == nT - 2) cp_wait0(); else cp_wait1();
            __syncthreads();
            if (t + 3 < nT) issue((t + 3) % NSTG, (t + 3) * BK);
            ldsm_half((t + 1) % NSTG, 0, 0);
        }
        mma_half(1);
    }

    // ---- Epilogue: each warp covers 64 rows x 64 cols ----
    const int lgrp = lane >> 2;
    const int lth  = lane & 3;
    const int act  = sg.act;
#pragma unroll
    for (int nt = 0; nt < 8; ++nt) {
        int col  = bn + wn * 64 + nt * 8 + 2 * lth;
        int cseg = col / p.segN;
        int lcol = col - cseg * p.segN;
        const float* bp = (cseg == 0) ? sg.b0 : (cseg == 1) ? sg.b1 : sg.b2;
        float bx = __ldg(bp + lcol);
        float by = __ldg(bp + lcol + 1);
#pragma unroll
        for (int mt = 0; mt < 4; ++mt) {
            int row = bm + wm * 64 + mt * 16 + lgrp;
            float v0x = acc[mt][nt][0] + bx, v0y = acc[mt][nt][1] + by;
            float v1x = acc[mt][nt][2] + bx, v1y = acc[mt][nt][3] + by;
            if (act <= 1) {
                if (act == 1) {
                    v0x = fmaxf(v0x, 0.f); v0y = fmaxf(v0y, 0.f);
                    v1x = fmaxf(v1x, 0.f); v1y = fmaxf(v1y, 0.f);
                }
                __half2 h0 = __floats2half2_rn(v0x, v0y);
                __half2 h1 = __floats2half2_rn(v1x, v1y);
                *reinterpret_cast<__half2*>(sg.Ch + (size_t)row * N + col)       = h0;
                *reinterpret_cast<__half2*>(sg.Ch + (size_t)(row + 8) * N + col) = h1;
            } else {
                if (cseg == 1) {
                    v0x = (v0x > 20.f) ? v0x : log1pf(__expf(v0x));
                    v0y = (v0y > 20.f) ? v0y : log1pf(__expf(v0y));
                    v1x = (v1x > 20.f) ? v1x : log1pf(__expf(v1x));
                    v1y = (v1y > 20.f) ? v1y : log1pf(__expf(v1y));
                }
                float* dst = sg.Cf + (size_t)cseg * ((size_t)B_ * NH)
                                   + (size_t)row * NH + lcol;
                *reinterpret_cast<float2*>(dst)                  = make_float2(v0x, v0y);
                *reinterpret_cast<float2*>(dst + (size_t)8 * NH) = make_float2(v1x, v1y);
            }
        }
    }
    gdc_launch();
}

// ============================================================================
// f32 -> f16 conversion (batched pointer table, up to 4 tensors per launch)
// ============================================================================
struct ConvArgs {
    const float4* src[4];
    __half2*      dst[4];
    int           end[4];
};

__global__ void conv_kernel(const __grid_constant__ ConvArgs a)
{
    gdc_wait();
    int i = blockIdx.x * blockDim.x + threadIdx.x;
    int prev = 0;
#pragma unroll
    for (int j = 0; j < 4; ++j) {
        if (i < a.end[j]) {
            int k = i - prev;
            float4 v = a.src[j][k];
            a.dst[j][2 * k]     = __floats2half2_rn(v.x, v.y);
            a.dst[j][2 * k + 1] = __floats2half2_rn(v.z, v.w);
            break;
        }
        prev = a.end[j];
    }
    gdc_launch();
}

// ============================================================================
// GRU gate fusion — fp16 gi/gh inputs, 8 elements per thread
// ============================================================================
__global__ void gru_gate_kernel(const __half2* __restrict__ gi,
                                const __half2* __restrict__ gh,
                                const float4* __restrict__ hprev,
                                float4* __restrict__ hnew,
                                __half2* __restrict__ hh,
                                __half2* __restrict__ htanhh)
{
    gdc_wait();
    int idx = blockIdx.x * blockDim.x + threadIdx.x;
    if (idx < B_ * H_ / 8) {
        int b  = idx >> 7;
        int jj = idx & 127;
        const int HH = H_ / 2;
        const __half2* gib = gi + (size_t)b * (3 * HH) + jj * 4;
        const __half2* ghb = gh + (size_t)b * (3 * HH) + jj * 4;

        uint4 irU = *reinterpret_cast<const uint4*>(gib);
        uint4 izU = *reinterpret_cast<const uint4*>(gib + HH);
        uint4 inU = *reinterpret_cast<const uint4*>(gib + 2 * HH);
        uint4 hrU = *reinterpret_cast<const uint4*>(ghb);
        uint4 hzU = *reinterpret_cast<const uint4*>(ghb + HH);
        uint4 hnU = *reinterpret_cast<const uint4*>(ghb + 2 * HH);
        const __half2* irp = reinterpret_cast<const __half2*>(&irU);
        const __half2* izp = reinterpret_cast<const __half2*>(&izU);
        const __half2* inp = reinterpret_cast<const __half2*>(&inU);
        const __half2* hrp = reinterpret_cast<const __half2*>(&hrU);
        const __half2* hzp = reinterpret_cast<const __half2*>(&hzU);
        const __half2* hnp = reinterpret_cast<const __half2*>(&hnU);

        float4 hp0 = hprev[2 * idx];
        float4 hp1 = hprev[2 * idx + 1];
        float hpv[8] = { hp0.x, hp0.y, hp0.z, hp0.w, hp1.x, hp1.y, hp1.z, hp1.w };

        float hres[8];
        __half2 hhv[4], htv[4];
#pragma unroll
        for (int q = 0; q < 4; ++q) {
            float2 ir = __half22float2(irp[q]);
            float2 iz = __half22float2(izp[q]);
            float2 in_ = __half22float2(inp[q]);
            float2 hr = __half22float2(hrp[q]);
            float2 hz = __half22float2(hzp[q]);
            float2 hn = __half22float2(hnp[q]);
            float r0 = sigma_f(ir.x + hr.x), z0 = sigma_f(iz.x + hz.x);
            float n0 = tanha(fmaf(r0, hn.x, in_.x));
            float h0 = fmaf(z0, hpv[2 * q] - n0, n0);
            float r1 = sigma_f(ir.y + hr.y), z1 = sigma_f(iz.y + hz.y);
            float n1 = tanha(fmaf(r1, hn.y, in_.y));
            float h1 = fmaf(z1, hpv[2 * q + 1] - n1, n1);
            hres[2 * q] = h0; hres[2 * q + 1] = h1;
            hhv[q] = __floats2half2_rn(h0, h1);
            htv[q] = __floats2half2_rn(tanha(h0), tanha(h1));
        }

        hnew[2 * idx]     = make_float4(hres[0], hres[1], hres[2], hres[3]);
        hnew[2 * idx + 1] = make_float4(hres[4], hres[5], hres[6], hres[7]);
        if (hh)
            *reinterpret_cast<uint4*>(hh + 4 * (size_t)idx) =
                *reinterpret_cast<uint4*>(hhv);
        if (htanhh)
            *reinterpret_cast<uint4*>(htanhh + 4 * (size_t)idx) =
                *reinterpret_cast<uint4*>(htv);
    }
    gdc_launch();
}

__global__ void pi_softmax_kernel(float* __restrict__ pi)
{
    gdc_wait();
    int idx = blockIdx.x * blockDim.x + threadIdx.x;
    if (idx < B_ * O_) {
        int b = idx >> 8;
        int o = idx & (O_ - 1);
        float* p = pi + (size_t)b * NH + o;
        float v0 = p[0], v1 = p[O_], v2 = p[2 * O_];
        float m = fmaxf(v0, fmaxf(v1, v2));
        float e0 = __expf(v0 - m), e1 = __expf(v1 - m), e2 = __expf(v2 - m);
        float inv = 1.f / (e0 + e1 + e2);
        p[0] = e0 * inv; p[O_] = e1 * inv; p[2 * O_] = e2 * inv;
    }
    gdc_launch();
}

// ============================================================================
// Host
// ============================================================================
template <typename KernelT, typename... Args>
static inline void launch_pdl(KernelT kernel, dim3 grid, dim3 block,
                              size_t smem, Args... args)
{
    cudaLaunchConfig_t cfg = {};
    cfg.gridDim = grid;
    cfg.blockDim = block;
    cfg.dynamicSmemBytes = smem;
    cudaLaunchAttribute attr[1];
    attr[0].id = cudaLaunchAttributeProgrammaticStreamSerialization;
    attr[0].val.programmaticStreamSerializationAllowed = 1;
    cfg.attrs = attr;
    cfg.numAttrs = 1;
    cudaLaunchKernelEx(&cfg, kernel, args...);
}

extern "C" void kernel_launch(void* const* d_in, const int* in_sizes, int n_in,
                              void* d_out, int out_size)
{
    const float* x       = (const float*)d_in[0];
    const float* hidden  = (const float*)d_in[1];
    const float* i2d_w   = (const float*)d_in[2];
    const float* i2d_b   = (const float*)d_in[3];
    const float* w_ih    = (const float*)d_in[4];
    const float* w_hh    = (const float*)d_in[5];
    const float* b_ih    = (const float*)d_in[6];
    const float* b_hh    = (const float*)d_in[7];
    const float* mu_w    = (const float*)d_in[8];
    const float* mu_b    = (const float*)d_in[9];
    const float* sigma_w = (const float*)d_in[10];
    const float* sigma_b = (const float*)d_in[11];
    const float* pi_w    = (const float*)d_in[12];
    const float* pi_b    = (const float*)d_in[13];

    float* out = (float*)d_out;
    const size_t head_sz = (size_t)B_ * NH;
    float* out_pi     = out + 2 * head_sz;
    float* out_hidden = out + 3 * head_sz;

    __half *xh, *hidh, *i2dwh, *wihh, *whhh, *headwh, *h1h, *gih, *ghh, *h2h, *houth;
    cudaGetSymbolAddress((void**)&xh,     g_xh);
    cudaGetSymbolAddress((void**)&hidh,   g_hidh);
    cudaGetSymbolAddress((void**)&i2dwh,  g_i2dwh);
    cudaGetSymbolAddress((void**)&wihh,   g_wihh);
    cudaGetSymbolAddress((void**)&whhh,   g_whhh);
    cudaGetSymbolAddress((void**)&headwh, g_headwh);
    cudaGetSymbolAddress((void**)&h1h,    g_h1h);
    cudaGetSymbolAddress((void**)&gih,    g_gih);
    cudaGetSymbolAddress((void**)&ghh,    g_ghh);
    cudaGetSymbolAddress((void**)&h2h,    g_h2h);
    cudaGetSymbolAddress((void**)&houth,  g_houth);

    const size_t lw = (size_t)3 * H_ * H_;
    const size_t lb = (size_t)3 * H_;
    const size_t lh = (size_t)B_ * H_;

    static bool attr_set = false;
    if (!attr_set) {
        cudaFuncSetAttribute(gemm_f16,
                             cudaFuncAttributeMaxDynamicSharedMemorySize, SMEM_BYTES);
        attr_set = true;
    }

    const int gateGrid = (B_ * H_ / 8) / 256;   // 2048
    const int smGrid   = (B_ * O_) / 256;       // 4096

    // ---- 1,2) conversion prepass ----
    {
        ConvArgs ca;
        int e = 0, j = 0;
        auto add = [&](const float* s, __half* d, size_t n) {
            ca.src[j] = (const float4*)s; ca.dst[j] = (__half2*)d;
            e += (int)(n / 4); ca.end[j] = e; ++j;
        };
        add(x,      xh,    (size_t)B_ * IN_);
        add(hidden, hidh,  (size_t)L_ * B_ * H_);
        add(i2d_w,  i2dwh, (size_t)H_ * IN_);
        add(w_ih,   wihh,  (size_t)L_ * lw);
        launch_pdl(conv_kernel, dim3((e + 255) / 256), dim3(256), 0, ca);
    }
    {
        ConvArgs ca;
        int e = 0, j = 0;
        auto add = [&](const float* s, __half* d, size_t n) {
            ca.src[j] = (const float4*)s; ca.dst[j] = (__half2*)d;
            e += (int)(n / 4); ca.end[j] = e; ++j;
        };
        add(w_hh,    whhh,  (size_t)L_ * lw);
        add(mu_w,    headwh,                       (size_t)NH * H_);
        add(sigma_w, headwh + (size_t)NH * H_,     (size_t)NH * H_);
        add(pi_w,    headwh + (size_t)2 * NH * H_, (size_t)NH * H_);
        launch_pdl(conv_kernel, dim3((e + 255) / 256), dim3(256), 0, ca);
    }

    // ---- 3) i2d: h1 = relu(x @ i2d_w^T + b) -> half ----
    {
        GemmP p;
        p.s[0] = { xh, i2dwh, i2d_b, i2d_b, i2d_b, nullptr, h1h, 1 };
        p.s[1] = p.s[0];
        p.xTiles = H_ / BN; p.N = H_; p.K = IN_; p.segN = H_;
        launch_pdl(gemm_f16, dim3(p.xTiles, B_ / BM), dim3(128), SMEM_BYTES, p);
    }

    // ---- 4) GRU layer 0: gh | gi fused ----
    {
        GemmP p;
        p.s[0] = { hidh, whhh, b_hh, b_hh, b_hh, nullptr, ghh, 0 };
        p.s[1] = { h1h,  wihh, b_ih, b_ih, b_ih, nullptr, gih, 0 };
        p.xTiles = 3 * H_ / BN; p.N = 3 * H_; p.K = H_; p.segN = 3 * H_;
        launch_pdl(gemm_f16, dim3(2 * p.xTiles, B_ / BM), dim3(128), SMEM_BYTES, p);
    }
    // ---- 5) gate 0 ----
    launch_pdl(gru_gate_kernel, dim3(gateGrid), dim3(256), 0,
               (const __half2*)gih, (const __half2*)ghh,
               (const float4*)hidden,
               (float4*)out_hidden, (__half2*)h2h, (__half2*)nullptr);

    // ---- 6) GRU layer 1: gh | gi fused  (ncu capture target) ----
    {
        GemmP p;
        p.s[0] = { hidh + lh, whhh + lw, b_hh + lb, b_hh + lb, b_hh + lb, nullptr, ghh, 0 };
        p.s[1] = { h2h,       wihh + lw, b_ih + lb, b_ih + lb, b_ih + lb, nullptr, gih, 0 };
        p.xTiles = 3 * H_ / BN; p.N = 3 * H_; p.K = H_; p.segN = 3 * H_;
        launch_pdl(gemm_f16, dim3(2 * p.xTiles, B_ / BM), dim3(128), SMEM_BYTES, p);
    }
    // ---- 7) gate 1 ----
    launch_pdl(gru_gate_kernel, dim3(gateGrid), dim3(256), 0,
               (const __half2*)gih, (const __half2*)ghh,
               (const float4*)(hidden + lh),
               (float4*)(out_hidden + lh), (__half2*)nullptr, (__half2*)houth);

    // ---- 8) MDN heads: one fused GEMM (mu | sigma | pi), N = 2304 ----
    {
        GemmP p;
        p.s[0] = { houth, headwh, mu_b, sigma_b, pi_b, out, nullptr, 2 };
        p.s[1] = p.s[0];
        p.xTiles = NHEADS3 / BN; p.N = NHEADS3; p.K = H_; p.segN = NH;
        launch_pdl(gemm_f16, dim3(p.xTiles, B_ / BM), dim3(128), SMEM_BYTES, p);
    }

    // ---- 9) pi softmax ----
    launch_pdl(pi_softmax_kernel, dim3(smGrid), dim3(256), 0, out_pi);
}

// round 15
// speedup vs baseline: 1.0444x; 1.0444x over previous
#include <cuda_runtime.h>
#include <cuda_fp16.h>
#include <math.h>
#include <stdint.h>

// ============================================================================
// Problem constants
// ============================================================================
#define B_  4096
#define IN_ 512
#define H_  1024
#define O_  256
#define L_  2
#define G_  3
#define NH  (G_ * O_)        // 768 per head
#define NHEADS3 (3 * NH)     // 2304 fused head columns

// ============================================================================
// GEMM tiling: 128x128 block, 8 warps {2M x 4N}, 64x32 warp tile, BK=64
// ============================================================================
#define BM 128
#define BN 128
#define BK 64
#define PH 72                           // smem pitch in halves (144 B rows)
#define ATB (BM * PH * 2)               // 18432 B per operand tile
#define STG_BYTES (2 * ATB)             // 36864 (A + W per stage)
#define NSTG 3
#define SMEM_BYTES (NSTG * STG_BYTES)   // 110592

// ============================================================================
// Scratch (device globals)
// ============================================================================
static __device__ __align__(256) __half g_xh    [(size_t)B_ * IN_];
static __device__ __align__(256) __half g_hidh  [(size_t)L_ * B_ * H_];
static __device__ __align__(256) __half g_i2dwh [(size_t)H_ * IN_];
static __device__ __align__(256) __half g_wihh  [(size_t)L_ * 3 * H_ * H_];
static __device__ __align__(256) __half g_whhh  [(size_t)L_ * 3 * H_ * H_];
static __device__ __align__(256) __half g_headwh[(size_t)NHEADS3 * H_];
static __device__ __align__(256) __half g_h1h   [(size_t)B_ * H_];
static __device__ __align__(256) __half g_gih0  [(size_t)B_ * 3 * H_];
static __device__ __align__(256) __half g_ghh0  [(size_t)B_ * 3 * H_];
static __device__ __align__(256) __half g_gih1  [(size_t)B_ * 3 * H_];
static __device__ __align__(256) __half g_ghh1  [(size_t)B_ * 3 * H_];
static __device__ __align__(256) __half g_h2h   [(size_t)B_ * H_];
static __device__ __align__(256) __half g_houth [(size_t)B_ * H_];

// ============================================================================
// PTX helpers
// ============================================================================
__device__ __forceinline__ void gdc_wait() {
    asm volatile("griddepcontrol.wait;" ::: "memory");
}
__device__ __forceinline__ void gdc_launch() {
    asm volatile("griddepcontrol.launch_dependents;" ::: "memory");
}

__device__ __forceinline__ void cp_async16(uint32_t saddr, const void* gptr) {
    asm volatile("cp.async.cg.shared.global [%0], [%1], 16;"
                 :: "r"(saddr), "l"(gptr) : "memory");
}
__device__ __forceinline__ void cp_commit() {
    asm volatile("cp.async.commit_group;" ::: "memory");
}
__device__ __forceinline__ void cp_wait2() {
    asm volatile("cp.async.wait_group 2;" ::: "memory");
}
__device__ __forceinline__ void cp_wait1() {
    asm volatile("cp.async.wait_group 1;" ::: "memory");
}
__device__ __forceinline__ void cp_wait0() {
    asm volatile("cp.async.wait_group 0;" ::: "memory");
}

#define LDSM4(r, a) \
    asm volatile("ldmatrix.sync.aligned.m8n8.x4.shared.b16 {%0,%1,%2,%3}, [%4];" \
        : "=r"((r)[0]), "=r"((r)[1]), "=r"((r)[2]), "=r"((r)[3]) : "r"(a))

__device__ __forceinline__ void mma_f16(float c[4], const uint32_t a[4],
                                        uint32_t b0, uint32_t b1) {
    asm volatile(
        "mma.sync.aligned.m16n8k16.row.col.f32.f16.f16.f32 "
        "{%0,%1,%2,%3}, {%4,%5,%6,%7}, {%8,%9}, {%0,%1,%2,%3};"
        : "+f"(c[0]), "+f"(c[1]), "+f"(c[2]), "+f"(c[3])
        : "r"(a[0]), "r"(a[1]), "r"(a[2]), "r"(a[3]), "r"(b0), "r"(b1));
}

__device__ __forceinline__ float tanha(float x) {
    float y;
    asm("tanh.approx.f32 %0, %1;" : "=f"(y) : "f"(x));
    return y;
}
__device__ __forceinline__ float sigma_f(float x) {
    return fmaf(0.5f, tanha(0.5f * x), 0.5f);
}

// ============================================================================
// Per-launch segment table (up to 3 block-level segments, same N/K shape)
// ============================================================================
struct Seg {
    const __half* A;
    const __half* W;
    const float*  b0;
    const float*  b1;
    const float*  b2;
    float*        Cf;
    __half*       Ch;
    int           act;     // 0 half out, 1 relu->half, 2 heads f32 (softplus seg1)
};
struct GemmP {
    Seg s[3];
    int xTiles;            // N-tiles per segment
    int N;                 // columns per segment (C row stride)
    int K;
    int segN;              // column sub-segment width (for act==2 remap)
};

// ============================================================================
// GEMM (R13 core): 256 threads, 8 warps {2M x 4N}
// ============================================================================
__global__ __launch_bounds__(256, 2)
void gemm_f16(const __grid_constant__ GemmP p)
{
    extern __shared__ char smem_raw[];
    const uint32_t sbase = (uint32_t)__cvta_generic_to_shared(smem_raw);

    const int tid  = threadIdx.x;
    const int lane = tid & 31;
    const int wid  = tid >> 5;
    const int wm   = wid & 1;
    const int wn   = wid >> 1;

    int segi = blockIdx.x / p.xTiles;
    if (segi > 2) segi = 2;
    const int bn   = (blockIdx.x - segi * p.xTiles) * BN;
    const int bm   = blockIdx.y * BM;
    const Seg sg   = p.s[segi];
    const int K    = p.K;
    const int N    = p.N;

    float acc[4][4][4];
#pragma unroll
    for (int i = 0; i < 4; ++i)
#pragma unroll
        for (int j = 0; j < 4; ++j)
#pragma unroll
            for (int q = 0; q < 4; ++q) acc[i][j][q] = 0.f;

    const __half* __restrict__ Ap = sg.A;
    const __half* __restrict__ Wp = sg.W;
    auto issue = [&](int stg, int kt) {
        uint32_t sa = sbase + stg * STG_BYTES;
        uint32_t sb = sa + ATB;
#pragma unroll
        for (int i = 0; i < 4; ++i) {
            int idx = tid + i * 256;
            int row = idx >> 3;
            int c8  = (idx & 7) << 3;
            uint32_t doff = (uint32_t)(row * PH + c8) * 2;
            cp_async16(sa + doff, Ap + (size_t)(bm + row) * K + kt + c8);
            cp_async16(sb + doff, Wp + (size_t)(bn + row) * K + kt + c8);
        }
        cp_commit();
    };

    gdc_wait();

    const int nT = K / BK;
    issue(0, 0);
    issue(1, BK);
    issue(2, 2 * BK);

    const uint32_t aOff = (uint32_t)(((wm * 64 + (lane & 15)) * PH +
                                      ((lane >> 4) << 3)) * 2);
    const uint32_t bOff = (uint32_t)(((wn * 32 + ((lane >> 4) << 3) + (lane & 7)) * PH +
                                      (((lane >> 3) & 1) << 3)) * 2);

    uint32_t afb[2][4][4];
    uint32_t bfb[2][2][4];

    auto ldsm_half = [&](int s, int kk, int bsel) {
        uint32_t sa = sbase + s * STG_BYTES;
        uint32_t sb = sa + ATB;
#pragma unroll
        for (int mt = 0; mt < 4; ++mt)
            LDSM4(afb[bsel][mt], sa + aOff + (uint32_t)(mt * 16 * PH + kk) * 2);
#pragma unroll
        for (int pq = 0; pq < 2; ++pq)
            LDSM4(bfb[bsel][pq], sb + bOff + (uint32_t)(pq * 16 * PH + kk) * 2);
    };
    auto mma_half = [&](int b) {
#pragma unroll
        for (int mt = 0; mt < 4; ++mt)
#pragma unroll
            for (int nt = 0; nt < 4; ++nt)
                mma_f16(acc[mt][nt], afb[b][mt],
                        bfb[b][nt >> 1][(nt & 1) * 2],
                        bfb[b][nt >> 1][(nt & 1) * 2 + 1]);
    };

    cp_wait2();
    __syncthreads();
    ldsm_half(0, 0, 0);

    for (int t = 0; t < nT; ++t) {
        const int s = t % NSTG;
        ldsm_half(s, 16, 1);
        mma_half(0);
        ldsm_half(s, 32, 0);
        mma_half(1);
        ldsm_half(s, 48, 1);
        mma_half(0);
        if (t + 1 < nT) {
            if (t == nT - 2) cp_wait0(); else cp_wait1();
            __syncthreads();
            if (t + 3 < nT) issue((t + 3) % NSTG, (t + 3) * BK);
            ldsm_half((t + 1) % NSTG, 0, 0);
        }
        mma_half(1);
    }

    // ---- Epilogue ----
    const int lgrp = lane >> 2;
    const int lth  = lane & 3;
    const int act  = sg.act;
#pragma unroll
    for (int nt = 0; nt < 4; ++nt) {
        int col  = bn + wn * 32 + nt * 8 + 2 * lth;
        int cseg = col / p.segN;
        int lcol = col - cseg * p.segN;
        const float* bp = (cseg == 0) ? sg.b0 : (cseg == 1) ? sg.b1 : sg.b2;
        float bx = __ldg(bp + lcol);
        float by = __ldg(bp + lcol + 1);
#pragma unroll
        for (int mt = 0; mt < 4; ++mt) {
            int row = bm + wm * 64 + mt * 16 + lgrp;
            float v0x = acc[mt][nt][0] + bx, v0y = acc[mt][nt][1] + by;
            float v1x = acc[mt][nt][2] + bx, v1y = acc[mt][nt][3] + by;
            if (act <= 1) {
                if (act == 1) {
                    v0x = fmaxf(v0x, 0.f); v0y = fmaxf(v0y, 0.f);
                    v1x = fmaxf(v1x, 0.f); v1y = fmaxf(v1y, 0.f);
                }
                __half2 h0 = __floats2half2_rn(v0x, v0y);
                __half2 h1 = __floats2half2_rn(v1x, v1y);
                *reinterpret_cast<__half2*>(sg.Ch + (size_t)row * N + col)       = h0;
                *reinterpret_cast<__half2*>(sg.Ch + (size_t)(row + 8) * N + col) = h1;
            } else {
                if (cseg == 1) {
                    v0x = (v0x > 20.f) ? v0x : log1pf(__expf(v0x));
                    v0y = (v0y > 20.f) ? v0y : log1pf(__expf(v0y));
                    v1x = (v1x > 20.f) ? v1x : log1pf(__expf(v1x));
                    v1y = (v1y > 20.f) ? v1y : log1pf(__expf(v1y));
                }
                float* dst = sg.Cf + (size_t)cseg * ((size_t)B_ * NH)
                                   + (size_t)row * NH + lcol;
                *reinterpret_cast<float2*>(dst)                  = make_float2(v0x, v0y);
                *reinterpret_cast<float2*>(dst + (size_t)8 * NH) = make_float2(v1x, v1y);
            }
        }
    }
    gdc_launch();
}

// ============================================================================
// f32 -> f16 conversion: 8 tensors in one launch
// ============================================================================
struct ConvArgs {
    const float4* src[8];
    __half2*      dst[8];
    int           end[8];
};

__global__ void conv_kernel(const __grid_constant__ ConvArgs a)
{
    gdc_wait();
    int i = blockIdx.x * blockDim.x + threadIdx.x;
    int prev = 0;
#pragma unroll
    for (int j = 0; j < 8; ++j) {
        if (i < a.end[j]) {
            int k = i - prev;
            float4 v = a.src[j][k];
            a.dst[j][2 * k]     = __floats2half2_rn(v.x, v.y);
            a.dst[j][2 * k + 1] = __floats2half2_rn(v.z, v.w);
            break;
        }
        prev = a.end[j];
    }
    gdc_launch();
}

// ============================================================================
// GRU gate fusion — fp16 gi/gh inputs, 8 elements per thread
// ============================================================================
__global__ void gru_gate_kernel(const __half2* __restrict__ gi,
                                const __half2* __restrict__ gh,
                                const float4* __restrict__ hprev,
                                float4* __restrict__ hnew,
                                __half2* __restrict__ hh,
                                __half2* __restrict__ htanhh)
{
    gdc_wait();
    int idx = blockIdx.x * blockDim.x + threadIdx.x;
    if (idx < B_ * H_ / 8) {
        int b  = idx >> 7;
        int jj = idx & 127;
        const int HH = H_ / 2;
        const __half2* gib = gi + (size_t)b * (3 * HH) + jj * 4;
        const __half2* ghb = gh + (size_t)b * (3 * HH) + jj * 4;

        uint4 irU = *reinterpret_cast<const uint4*>(gib);
        uint4 izU = *reinterpret_cast<const uint4*>(gib + HH);
        uint4 inU = *reinterpret_cast<const uint4*>(gib + 2 * HH);
        uint4 hrU = *reinterpret_cast<const uint4*>(ghb);
        uint4 hzU = *reinterpret_cast<const uint4*>(ghb + HH);
        uint4 hnU = *reinterpret_cast<const uint4*>(ghb + 2 * HH);
        const __half2* irp = reinterpret_cast<const __half2*>(&irU);
        const __half2* izp = reinterpret_cast<const __half2*>(&izU);
        const __half2* inp = reinterpret_cast<const __half2*>(&inU);
        const __half2* hrp = reinterpret_cast<const __half2*>(&hrU);
        const __half2* hzp = reinterpret_cast<const __half2*>(&hzU);
        const __half2* hnp = reinterpret_cast<const __half2*>(&hnU);

        float4 hp0 = hprev[2 * idx];
        float4 hp1 = hprev[2 * idx + 1];
        float hpv[8] = { hp0.x, hp0.y, hp0.z, hp0.w, hp1.x, hp1.y, hp1.z, hp1.w };

        float hres[8];
        __half2 hhv[4], htv[4];
#pragma unroll
        for (int q = 0; q < 4; ++q) {
            float2 ir = __half22float2(irp[q]);
            float2 iz = __half22float2(izp[q]);
            float2 in_ = __half22float2(inp[q]);
            float2 hr = __half22float2(hrp[q]);
            float2 hz = __half22float2(hzp[q]);
            float2 hn = __half22float2(hnp[q]);
            float r0 = sigma_f(ir.x + hr.x), z0 = sigma_f(iz.x + hz.x);
            float n0 = tanha(fmaf(r0, hn.x, in_.x));
            float h0 = fmaf(z0, hpv[2 * q] - n0, n0);
            float r1 = sigma_f(ir.y + hr.y), z1 = sigma_f(iz.y + hz.y);
            float n1 = tanha(fmaf(r1, hn.y, in_.y));
            float h1 = fmaf(z1, hpv[2 * q + 1] - n1, n1);
            hres[2 * q] = h0; hres[2 * q + 1] = h1;
            hhv[q] = __floats2half2_rn(h0, h1);
            htv[q] = __floats2half2_rn(tanha(h0), tanha(h1));
        }

        hnew[2 * idx]     = make_float4(hres[0], hres[1], hres[2], hres[3]);
        hnew[2 * idx + 1] = make_float4(hres[4], hres[5], hres[6], hres[7]);
        if (hh)
            *reinterpret_cast<uint4*>(hh + 4 * (size_t)idx) =
                *reinterpret_cast<uint4*>(hhv);
        if (htanhh)
            *reinterpret_cast<uint4*>(htanhh + 4 * (size_t)idx) =
                *reinterpret_cast<uint4*>(htv);
    }
    gdc_launch();
}

__global__ void pi_softmax_kernel(float* __restrict__ pi)
{
    gdc_wait();
    int idx = blockIdx.x * blockDim.x + threadIdx.x;
    if (idx < B_ * O_) {
        int b = idx >> 8;
        int o = idx & (O_ - 1);
        float* p = pi + (size_t)b * NH + o;
        float v0 = p[0], v1 = p[O_], v2 = p[2 * O_];
        float m = fmaxf(v0, fmaxf(v1, v2));
        float e0 = __expf(v0 - m), e1 = __expf(v1 - m), e2 = __expf(v2 - m);
        float inv = 1.f / (e0 + e1 + e2);
        p[0] = e0 * inv; p[O_] = e1 * inv; p[2 * O_] = e2 * inv;
    }
    gdc_launch();
}

// ============================================================================
// Host
// ============================================================================
template <typename KernelT, typename... Args>
static inline void launch_pdl(KernelT kernel, dim3 grid, dim3 block,
                              size_t smem, Args... args)
{
    cudaLaunchConfig_t cfg = {};
    cfg.gridDim = grid;
    cfg.blockDim = block;
    cfg.dynamicSmemBytes = smem;
    cudaLaunchAttribute attr[1];
    attr[0].id = cudaLaunchAttributeProgrammaticStreamSerialization;
    attr[0].val.programmaticStreamSerializationAllowed = 1;
    cfg.attrs = attr;
    cfg.numAttrs = 1;
    cudaLaunchKernelEx(&cfg, kernel, args...);
}

extern "C" void kernel_launch(void* const* d_in, const int* in_sizes, int n_in,
                              void* d_out, int out_size)
{
    const float* x       = (const float*)d_in[0];
    const float* hidden  = (const float*)d_in[1];
    const float* i2d_w   = (const float*)d_in[2];
    const float* i2d_b   = (const float*)d_in[3];
    const float* w_ih    = (const float*)d_in[4];
    const float* w_hh    = (const float*)d_in[5];
    const float* b_ih    = (const float*)d_in[6];
    const float* b_hh    = (const float*)d_in[7];
    const float* mu_w    = (const float*)d_in[8];
    const float* mu_b    = (const float*)d_in[9];
    const float* sigma_w = (const float*)d_in[10];
    const float* sigma_b = (const float*)d_in[11];
    const float* pi_w    = (const float*)d_in[12];
    const float* pi_b    = (const float*)d_in[13];

    float* out = (float*)d_out;
    const size_t head_sz = (size_t)B_ * NH;
    float* out_pi     = out + 2 * head_sz;
    float* out_hidden = out + 3 * head_sz;

    __half *xh, *hidh, *i2dwh, *wihh, *whhh, *headwh, *h1h;
    __half *gih0, *ghh0, *gih1, *ghh1, *h2h, *houth;
    cudaGetSymbolAddress((void**)&xh,     g_xh);
    cudaGetSymbolAddress((void**)&hidh,   g_hidh);
    cudaGetSymbolAddress((void**)&i2dwh,  g_i2dwh);
    cudaGetSymbolAddress((void**)&wihh,   g_wihh);
    cudaGetSymbolAddress((void**)&whhh,   g_whhh);
    cudaGetSymbolAddress((void**)&headwh, g_headwh);
    cudaGetSymbolAddress((void**)&h1h,    g_h1h);
    cudaGetSymbolAddress((void**)&gih0,   g_gih0);
    cudaGetSymbolAddress((void**)&ghh0,   g_ghh0);
    cudaGetSymbolAddress((void**)&gih1,   g_gih1);
    cudaGetSymbolAddress((void**)&ghh1,   g_ghh1);
    cudaGetSymbolAddress((void**)&h2h,    g_h2h);
    cudaGetSymbolAddress((void**)&houth,  g_houth);

    const size_t lw = (size_t)3 * H_ * H_;
    const size_t lb = (size_t)3 * H_;
    const size_t lh = (size_t)B_ * H_;

    static bool attr_set = false;
    if (!attr_set) {
        cudaFuncSetAttribute(gemm_f16,
                             cudaFuncAttributeMaxDynamicSharedMemorySize, SMEM_BYTES);
        attr_set = true;
    }

    const int gateGrid = (B_ * H_ / 8) / 256;   // 2048
    const int smGrid   = (B_ * O_) / 256;       // 4096

    // ---- 1) conversion prepass: all 8 tensors, ONE launch ----
    {
        ConvArgs ca;
        int e = 0, j = 0;
        auto add = [&](const float* s, __half* d, size_t n) {
            ca.src[j] = (const float4*)s; ca.dst[j] = (__half2*)d;
            e += (int)(n / 4); ca.end[j] = e; ++j;
        };
        add(x,       xh,    (size_t)B_ * IN_);
        add(hidden,  hidh,  (size_t)L_ * B_ * H_);
        add(i2d_w,   i2dwh, (size_t)H_ * IN_);
        add(w_ih,    wihh,  (size_t)L_ * lw);
        add(w_hh,    whhh,  (size_t)L_ * lw);
        add(mu_w,    headwh,                       (size_t)NH * H_);
        add(sigma_w, headwh + (size_t)NH * H_,     (size_t)NH * H_);
        add(pi_w,    headwh + (size_t)2 * NH * H_, (size_t)NH * H_);
        launch_pdl(conv_kernel, dim3((e + 255) / 256), dim3(256), 0, ca);
    }

    // ---- 2) i2d: h1 = relu(x @ i2d_w^T + b) -> half ----
    {
        GemmP p;
        p.s[0] = { xh, i2dwh, i2d_b, i2d_b, i2d_b, nullptr, h1h, 1 };
        p.s[1] = p.s[0]; p.s[2] = p.s[0];
        p.xTiles = H_ / BN; p.N = H_; p.K = IN_; p.segN = H_;
        launch_pdl(gemm_f16, dim3(p.xTiles, B_ / BM), dim3(256), SMEM_BYTES, p);
    }

    // ---- 3) BIG fused GEMM: gh0 | gi0 | gh1 (all shapes B x 3H x H) ----
    //     gh1 depends only on conv (hidh layer1 + whhh layer1) -> legal here.
    {
        GemmP p;
        p.s[0] = { hidh,      whhh,      b_hh,      b_hh,      b_hh,      nullptr, ghh0, 0 };
        p.s[1] = { h1h,       wihh,      b_ih,      b_ih,      b_ih,      nullptr, gih0, 0 };
        p.s[2] = { hidh + lh, whhh + lw, b_hh + lb, b_hh + lb, b_hh + lb, nullptr, ghh1, 0 };
        p.xTiles = 3 * H_ / BN; p.N = 3 * H_; p.K = H_; p.segN = 3 * H_;
        launch_pdl(gemm_f16, dim3(3 * p.xTiles, B_ / BM), dim3(256), SMEM_BYTES, p);
    }

    // ---- 4) gate 0 ----
    launch_pdl(gru_gate_kernel, dim3(gateGrid), dim3(256), 0,
               (const __half2*)gih0, (const __half2*)ghh0,
               (const float4*)hidden,
               (float4*)out_hidden, (__half2*)h2h, (__half2*)nullptr);

    // ---- 5) gi1 GEMM (A = h2h from gate0) ----
    {
        GemmP p;
        p.s[0] = { h2h, wihh + lw, b_ih + lb, b_ih + lb, b_ih + lb, nullptr, gih1, 0 };
        p.s[1] = p.s[0]; p.s[2] = p.s[0];
        p.xTiles = 3 * H_ / BN; p.N = 3 * H_; p.K = H_; p.segN = 3 * H_;
        launch_pdl(gemm_f16, dim3(p.xTiles, B_ / BM), dim3(256), SMEM_BYTES, p);
    }

    // ---- 6) gate 1 ----
    launch_pdl(gru_gate_kernel, dim3(gateGrid), dim3(256), 0,
               (const __half2*)gih1, (const __half2*)ghh1,
               (const float4*)(hidden + lh),
               (float4*)(out_hidden + lh), (__half2*)nullptr, (__half2*)houth);

    // ---- 7) MDN heads: one fused GEMM (mu | sigma | pi), N = 2304 ----
    {
        GemmP p;
        p.s[0] = { houth, headwh, mu_b, sigma_b, pi_b, out, nullptr, 2 };
        p.s[1] = p.s[0]; p.s[2] = p.s[0];
        p.xTiles = NHEADS3 / BN; p.N = NHEADS3; p.K = H_; p.segN = NH;
        launch_pdl(gemm_f16, dim3(p.xTiles, B_ / BM), dim3(256), SMEM_BYTES, p);
    }

    // ---- 8) pi softmax ----
    launch_pdl(pi_softmax_kernel, dim3(smGrid), dim3(256), 0, out_pi);
}

// round 16
// speedup vs baseline: 1.0573x; 1.0124x over previous
#include <cuda_runtime.h>
#include <cuda_fp16.h>
#include <math.h>
#include <stdint.h>

// ============================================================================
// Problem constants
// ============================================================================
#define B_  4096
#define IN_ 512
#define H_  1024
#define O_  256
#define L_  2
#define G_  3
#define NH  (G_ * O_)        // 768 per head
#define NHEADS3 (3 * NH)     // 2304 fused head columns

// ============================================================================
// GEMM tiling: 128x128 block, 8 warps {2M x 4N}, 64x32 warp tile, BK=64
// ============================================================================
#define BM 128
#define BN 128
#define BK 64
#define PH 72                           // smem pitch in halves (144 B rows)
#define ATB (BM * PH * 2)               // 18432 B per operand tile
#define STG_BYTES (2 * ATB)             // 36864 (A + W per stage)
#define NSTG 3
#define SMEM_BYTES (NSTG * STG_BYTES)   // 110592

// ============================================================================
// Scratch (device globals)
// ============================================================================
static __device__ __align__(256) __half g_xh    [(size_t)B_ * IN_];
static __device__ __align__(256) __half g_hidh  [(size_t)L_ * B_ * H_];
static __device__ __align__(256) __half g_i2dwh [(size_t)H_ * IN_];
static __device__ __align__(256) __half g_wihh  [(size_t)L_ * 3 * H_ * H_];
static __device__ __align__(256) __half g_whhh  [(size_t)L_ * 3 * H_ * H_];
static __device__ __align__(256) __half g_headwh[(size_t)NHEADS3 * H_];
static __device__ __align__(256) __half g_h1h   [(size_t)B_ * H_];
static __device__ __align__(256) __half g_gih0  [(size_t)B_ * 3 * H_];
static __device__ __align__(256) __half g_ghh0  [(size_t)B_ * 3 * H_];
static __device__ __align__(256) __half g_gih1  [(size_t)B_ * 3 * H_];
static __device__ __align__(256) __half g_ghh1  [(size_t)B_ * 3 * H_];
static __device__ __align__(256) __half g_h2h   [(size_t)B_ * H_];
static __device__ __align__(256) __half g_houth [(size_t)B_ * H_];

// ============================================================================
// PTX helpers
// ============================================================================
__device__ __forceinline__ void gdc_wait() {
    asm volatile("griddepcontrol.wait;" ::: "memory");
}
__device__ __forceinline__ void gdc_launch() {
    asm volatile("griddepcontrol.launch_dependents;" ::: "memory");
}

__device__ __forceinline__ void cp_async16(uint32_t saddr, const void* gptr) {
    asm volatile("cp.async.cg.shared.global [%0], [%1], 16;"
                 :: "r"(saddr), "l"(gptr) : "memory");
}
__device__ __forceinline__ void cp_commit() {
    asm volatile("cp.async.commit_group;" ::: "memory");
}
__device__ __forceinline__ void cp_wait2() {
    asm volatile("cp.async.wait_group 2;" ::: "memory");
}
__device__ __forceinline__ void cp_wait1() {
    asm volatile("cp.async.wait_group 1;" ::: "memory");
}
__device__ __forceinline__ void cp_wait0() {
    asm volatile("cp.async.wait_group 0;" ::: "memory");
}

#define LDSM4(r, a) \
    asm volatile("ldmatrix.sync.aligned.m8n8.x4.shared.b16 {%0,%1,%2,%3}, [%4];" \
        : "=r"((r)[0]), "=r"((r)[1]), "=r"((r)[2]), "=r"((r)[3]) : "r"(a))

__device__ __forceinline__ void mma_f16(float c[4], const uint32_t a[4],
                                        uint32_t b0, uint32_t b1) {
    asm volatile(
        "mma.sync.aligned.m16n8k16.row.col.f32.f16.f16.f32 "
        "{%0,%1,%2,%3}, {%4,%5,%6,%7}, {%8,%9}, {%0,%1,%2,%3};"
        : "+f"(c[0]), "+f"(c[1]), "+f"(c[2]), "+f"(c[3])
        : "r"(a[0]), "r"(a[1]), "r"(a[2]), "r"(a[3]), "r"(b0), "r"(b1));
}

__device__ __forceinline__ float tanha(float x) {
    float y;
    asm("tanh.approx.f32 %0, %1;" : "=f"(y) : "f"(x));
    return y;
}
__device__ __forceinline__ float sigma_f(float x) {
    return fmaf(0.5f, tanha(0.5f * x), 0.5f);
}

// ============================================================================
// Per-launch segment table (up to 3 block-level segments, same N/K shape)
// ============================================================================
struct Seg {
    const __half* A;
    const __half* W;
    const float*  b0;
    const float*  b1;
    const float*  b2;
    float*        Cf;
    __half*       Ch;
    int           act;     // 0 half out, 1 relu->half, 2 heads f32 (softplus seg1)
};
struct GemmP {
    Seg s[3];
    int xTiles;            // N-tiles per segment
    int N;                 // columns per segment (C row stride)
    int K;
    int segN;              // column sub-segment width (for act==2 remap)
};

// ============================================================================
// GEMM (best-known core): 256 threads, 8 warps {2M x 4N}
// ============================================================================
__global__ __launch_bounds__(256, 2)
void gemm_f16(const __grid_constant__ GemmP p)
{
    extern __shared__ char smem_raw[];
    const uint32_t sbase = (uint32_t)__cvta_generic_to_shared(smem_raw);

    const int tid  = threadIdx.x;
    const int lane = tid & 31;
    const int wid  = tid >> 5;
    const int wm   = wid & 1;
    const int wn   = wid >> 1;

    int segi = blockIdx.x / p.xTiles;
    if (segi > 2) segi = 2;
    const int bn   = (blockIdx.x - segi * p.xTiles) * BN;
    const int bm   = blockIdx.y * BM;
    const Seg sg   = p.s[segi];
    const int K    = p.K;
    const int N    = p.N;

    float acc[4][4][4];
#pragma unroll
    for (int i = 0; i < 4; ++i)
#pragma unroll
        for (int j = 0; j < 4; ++j)
#pragma unroll
            for (int q = 0; q < 4; ++q) acc[i][j][q] = 0.f;

    const __half* __restrict__ Ap = sg.A;
    const __half* __restrict__ Wp = sg.W;
    auto issue = [&](int stg, int kt) {
        uint32_t sa = sbase + stg * STG_BYTES;
        uint32_t sb = sa + ATB;
#pragma unroll
        for (int i = 0; i < 4; ++i) {
            int idx = tid + i * 256;
            int row = idx >> 3;
            int c8  = (idx & 7) << 3;
            uint32_t doff = (uint32_t)(row * PH + c8) * 2;
            cp_async16(sa + doff, Ap + (size_t)(bm + row) * K + kt + c8);
            cp_async16(sb + doff, Wp + (size_t)(bn + row) * K + kt + c8);
        }
        cp_commit();
    };

    gdc_wait();

    const int nT = K / BK;
    issue(0, 0);
    issue(1, BK);
    issue(2, 2 * BK);

    const uint32_t aOff = (uint32_t)(((wm * 64 + (lane & 15)) * PH +
                                      ((lane >> 4) << 3)) * 2);
    const uint32_t bOff = (uint32_t)(((wn * 32 + ((lane >> 4) << 3) + (lane & 7)) * PH +
                                      (((lane >> 3) & 1) << 3)) * 2);

    uint32_t afb[2][4][4];
    uint32_t bfb[2][2][4];

    auto ldsm_half = [&](int s, int kk, int bsel) {
        uint32_t sa = sbase + s * STG_BYTES;
        uint32_t sb = sa + ATB;
#pragma unroll
        for (int mt = 0; mt < 4; ++mt)
            LDSM4(afb[bsel][mt], sa + aOff + (uint32_t)(mt * 16 * PH + kk) * 2);
#pragma unroll
        for (int pq = 0; pq < 2; ++pq)
            LDSM4(bfb[bsel][pq], sb + bOff + (uint32_t)(pq * 16 * PH + kk) * 2);
    };
    auto mma_half = [&](int b) {
#pragma unroll
        for (int mt = 0; mt < 4; ++mt)
#pragma unroll
            for (int nt = 0; nt < 4; ++nt)
                mma_f16(acc[mt][nt], afb[b][mt],
                        bfb[b][nt >> 1][(nt & 1) * 2],
                        bfb[b][nt >> 1][(nt & 1) * 2 + 1]);
    };

    cp_wait2();
    __syncthreads();
    ldsm_half(0, 0, 0);

    for (int t = 0; t < nT; ++t) {
        const int s = t % NSTG;
        ldsm_half(s, 16, 1);
        mma_half(0);
        ldsm_half(s, 32, 0);
        mma_half(1);
        ldsm_half(s, 48, 1);
        mma_half(0);
        if (t + 1 < nT) {
            if (t == nT - 2) cp_wait0(); else cp_wait1();
            __syncthreads();
            if (t + 3 < nT) issue((t + 3) % NSTG, (t + 3) * BK);
            ldsm_half((t + 1) % NSTG, 0, 0);
        }
        mma_half(1);
    }

    // ---- Epilogue ----
    const int lgrp = lane >> 2;
    const int lth  = lane & 3;
    const int act  = sg.act;
#pragma unroll
    for (int nt = 0; nt < 4; ++nt) {
        int col  = bn + wn * 32 + nt * 8 + 2 * lth;
        int cseg = col / p.segN;
        int lcol = col - cseg * p.segN;
        const float* bp = (cseg == 0) ? sg.b0 : (cseg == 1) ? sg.b1 : sg.b2;
        float bx = __ldg(bp + lcol);
        float by = __ldg(bp + lcol + 1);
#pragma unroll
        for (int mt = 0; mt < 4; ++mt) {
            int row = bm + wm * 64 + mt * 16 + lgrp;
            float v0x = acc[mt][nt][0] + bx, v0y = acc[mt][nt][1] + by;
            float v1x = acc[mt][nt][2] + bx, v1y = acc[mt][nt][3] + by;
            if (act <= 1) {
                if (act == 1) {
                    v0x = fmaxf(v0x, 0.f); v0y = fmaxf(v0y, 0.f);
                    v1x = fmaxf(v1x, 0.f); v1y = fmaxf(v1y, 0.f);
                }
                __half2 h0 = __floats2half2_rn(v0x, v0y);
                __half2 h1 = __floats2half2_rn(v1x, v1y);
                *reinterpret_cast<__half2*>(sg.Ch + (size_t)row * N + col)       = h0;
                *reinterpret_cast<__half2*>(sg.Ch + (size_t)(row + 8) * N + col) = h1;
            } else {
                if (cseg == 1) {
                    v0x = (v0x > 20.f) ? v0x : log1pf(__expf(v0x));
                    v0y = (v0y > 20.f) ? v0y : log1pf(__expf(v0y));
                    v1x = (v1x > 20.f) ? v1x : log1pf(__expf(v1x));
                    v1y = (v1y > 20.f) ? v1y : log1pf(__expf(v1y));
                }
                float* dst = sg.Cf + (size_t)cseg * ((size_t)B_ * NH)
                                   + (size_t)row * NH + lcol;
                *reinterpret_cast<float2*>(dst)                  = make_float2(v0x, v0y);
                *reinterpret_cast<float2*>(dst + (size_t)8 * NH) = make_float2(v1x, v1y);
            }
        }
    }
    gdc_launch();
}

// ============================================================================
// f32 -> f16 conversion: 8 tensors in one launch (streaming reads)
// ============================================================================
struct ConvArgs {
    const float4* src[8];
    __half2*      dst[8];
    int           end[8];
};

__global__ void conv_kernel(const __grid_constant__ ConvArgs a)
{
    gdc_wait();
    int i = blockIdx.x * blockDim.x + threadIdx.x;
    int prev = 0;
#pragma unroll
    for (int j = 0; j < 8; ++j) {
        if (i < a.end[j]) {
            int k = i - prev;
            float4 v = __ldcs(&a.src[j][k]);      // read-once: evict-first
            a.dst[j][2 * k]     = __floats2half2_rn(v.x, v.y);
            a.dst[j][2 * k + 1] = __floats2half2_rn(v.z, v.w);
            break;
        }
        prev = a.end[j];
    }
    gdc_launch();
}

// ============================================================================
// GRU gate fusion — fp16 gi/gh inputs; streaming store for hnew (never re-read)
// ============================================================================
__global__ void gru_gate_kernel(const __half2* __restrict__ gi,
                                const __half2* __restrict__ gh,
                                const float4* __restrict__ hprev,
                                float4* __restrict__ hnew,
                                __half2* __restrict__ hh,
                                __half2* __restrict__ htanhh)
{
    gdc_wait();
    int idx = blockIdx.x * blockDim.x + threadIdx.x;
    if (idx < B_ * H_ / 8) {
        int b  = idx >> 7;
        int jj = idx & 127;
        const int HH = H_ / 2;
        const __half2* gib = gi + (size_t)b * (3 * HH) + jj * 4;
        const __half2* ghb = gh + (size_t)b * (3 * HH) + jj * 4;

        uint4 irU = __ldcs(reinterpret_cast<const uint4*>(gib));
        uint4 izU = __ldcs(reinterpret_cast<const uint4*>(gib + HH));
        uint4 inU = __ldcs(reinterpret_cast<const uint4*>(gib + 2 * HH));
        uint4 hrU = __ldcs(reinterpret_cast<const uint4*>(ghb));
        uint4 hzU = __ldcs(reinterpret_cast<const uint4*>(ghb + HH));
        uint4 hnU = __ldcs(reinterpret_cast<const uint4*>(ghb + 2 * HH));
        const __half2* irp = reinterpret_cast<const __half2*>(&irU);
        const __half2* izp = reinterpret_cast<const __half2*>(&izU);
        const __half2* inp = reinterpret_cast<const __half2*>(&inU);
        const __half2* hrp = reinterpret_cast<const __half2*>(&hrU);
        const __half2* hzp = reinterpret_cast<const __half2*>(&hzU);
        const __half2* hnp = reinterpret_cast<const __half2*>(&hnU);

        float4 hp0 = hprev[2 * idx];
        float4 hp1 = hprev[2 * idx + 1];
        float hpv[8] = { hp0.x, hp0.y, hp0.z, hp0.w, hp1.x, hp1.y, hp1.z, hp1.w };

        float hres[8];
        __half2 hhv[4], htv[4];
#pragma unroll
        for (int q = 0; q < 4; ++q) {
            float2 ir = __half22float2(irp[q]);
            float2 iz = __half22float2(izp[q]);
            float2 in_ = __half22float2(inp[q]);
            float2 hr = __half22float2(hrp[q]);
            float2 hz = __half22float2(hzp[q]);
            float2 hn = __half22float2(hnp[q]);
            float r0 = sigma_f(ir.x + hr.x), z0 = sigma_f(iz.x + hz.x);
            float n0 = tanha(fmaf(r0, hn.x, in_.x));
            float h0 = fmaf(z0, hpv[2 * q] - n0, n0);
            float r1 = sigma_f(ir.y + hr.y), z1 = sigma_f(iz.y + hz.y);
            float n1 = tanha(fmaf(r1, hn.y, in_.y));
            float h1 = fmaf(z1, hpv[2 * q + 1] - n1, n1);
            hres[2 * q] = h0; hres[2 * q + 1] = h1;
            hhv[q] = __floats2half2_rn(h0, h1);
            htv[q] = __floats2half2_rn(tanha(h0), tanha(h1));
        }

        __stcs(hnew + 2 * idx,     make_float4(hres[0], hres[1], hres[2], hres[3]));
        __stcs(hnew + 2 * idx + 1, make_float4(hres[4], hres[5], hres[6], hres[7]));
        if (hh)
            *reinterpret_cast<uint4*>(hh + 4 * (size_t)idx) =
                *reinterpret_cast<uint4*>(hhv);
        if (htanhh)
            *reinterpret_cast<uint4*>(htanhh + 4 * (size_t)idx) =
                *reinterpret_cast<uint4*>(htv);
    }
    gdc_launch();
}

// ============================================================================
// pi softmax — vectorized 4-wide over o
// ============================================================================
__global__ void pi_softmax_kernel(float* __restrict__ pi)
{
    gdc_wait();
    int idx = blockIdx.x * blockDim.x + threadIdx.x;   // [0, B*O/4)
    if (idx < B_ * O_ / 4) {
        int b  = idx >> 6;            // / (O_/4)
        int o4 = (idx & 63) << 2;
        float* p = pi + (size_t)b * NH + o4;
        float4 v0 = *reinterpret_cast<float4*>(p);
        float4 v1 = *reinterpret_cast<float4*>(p + O_);
        float4 v2 = *reinterpret_cast<float4*>(p + 2 * O_);
        float r0[4] = { v0.x, v0.y, v0.z, v0.w };
        float r1[4] = { v1.x, v1.y, v1.z, v1.w };
        float r2[4] = { v2.x, v2.y, v2.z, v2.w };
#pragma unroll
        for (int q = 0; q < 4; ++q) {
            float m = fmaxf(r0[q], fmaxf(r1[q], r2[q]));
            float e0 = __expf(r0[q] - m), e1 = __expf(r1[q] - m), e2 = __expf(r2[q] - m);
            float inv = 1.f / (e0 + e1 + e2);
            r0[q] = e0 * inv; r1[q] = e1 * inv; r2[q] = e2 * inv;
        }
        *reinterpret_cast<float4*>(p)          = make_float4(r0[0], r0[1], r0[2], r0[3]);
        *reinterpret_cast<float4*>(p + O_)     = make_float4(r1[0], r1[1], r1[2], r1[3]);
        *reinterpret_cast<float4*>(p + 2 * O_) = make_float4(r2[0], r2[1], r2[2], r2[3]);
    }
    gdc_launch();
}

// ============================================================================
// Host
// ============================================================================
template <typename KernelT, typename... Args>
static inline void launch_pdl(KernelT kernel, dim3 grid, dim3 block,
                              size_t smem, Args... args)
{
    cudaLaunchConfig_t cfg = {};
    cfg.gridDim = grid;
    cfg.blockDim = block;
    cfg.dynamicSmemBytes = smem;
    cudaLaunchAttribute attr[1];
    attr[0].id = cudaLaunchAttributeProgrammaticStreamSerialization;
    attr[0].val.programmaticStreamSerializationAllowed = 1;
    cfg.attrs = attr;
    cfg.numAttrs = 1;
    cudaLaunchKernelEx(&cfg, kernel, args...);
}

extern "C" void kernel_launch(void* const* d_in, const int* in_sizes, int n_in,
                              void* d_out, int out_size)
{
    const float* x       = (const float*)d_in[0];
    const float* hidden  = (const float*)d_in[1];
    const float* i2d_w   = (const float*)d_in[2];
    const float* i2d_b   = (const float*)d_in[3];
    const float* w_ih    = (const float*)d_in[4];
    const float* w_hh    = (const float*)d_in[5];
    const float* b_ih    = (const float*)d_in[6];
    const float* b_hh    = (const float*)d_in[7];
    const float* mu_w    = (const float*)d_in[8];
    const float* mu_b    = (const float*)d_in[9];
    const float* sigma_w = (const float*)d_in[10];
    const float* sigma_b = (const float*)d_in[11];
    const float* pi_w    = (const float*)d_in[12];
    const float* pi_b    = (const float*)d_in[13];

    float* out = (float*)d_out;
    const size_t head_sz = (size_t)B_ * NH;
    float* out_pi     = out + 2 * head_sz;
    float* out_hidden = out + 3 * head_sz;

    __half *xh, *hidh, *i2dwh, *wihh, *whhh, *headwh, *h1h;
    __half *gih0, *ghh0, *gih1, *ghh1, *h2h, *houth;
    cudaGetSymbolAddress((void**)&xh,     g_xh);
    cudaGetSymbolAddress((void**)&hidh,   g_hidh);
    cudaGetSymbolAddress((void**)&i2dwh,  g_i2dwh);
    cudaGetSymbolAddress((void**)&wihh,   g_wihh);
    cudaGetSymbolAddress((void**)&whhh,   g_whhh);
    cudaGetSymbolAddress((void**)&headwh, g_headwh);
    cudaGetSymbolAddress((void**)&h1h,    g_h1h);
    cudaGetSymbolAddress((void**)&gih0,   g_gih0);
    cudaGetSymbolAddress((void**)&ghh0,   g_ghh0);
    cudaGetSymbolAddress((void**)&gih1,   g_gih1);
    cudaGetSymbolAddress((void**)&ghh1,   g_ghh1);
    cudaGetSymbolAddress((void**)&h2h,    g_h2h);
    cudaGetSymbolAddress((void**)&houth,  g_houth);

    const size_t lw = (size_t)3 * H_ * H_;
    const size_t lb = (size_t)3 * H_;
    const size_t lh = (size_t)B_ * H_;

    static bool attr_set = false;
    if (!attr_set) {
        cudaFuncSetAttribute(gemm_f16,
                             cudaFuncAttributeMaxDynamicSharedMemorySize, SMEM_BYTES);
        attr_set = true;
    }

    const int gateGrid = (B_ * H_ / 8) / 256;    // 2048
    const int smGrid   = (B_ * O_ / 4) / 256;    // 1024

    // ---- 1) conversion prepass: all 8 tensors, ONE launch ----
    {
        ConvArgs ca;
        int e = 0, j = 0;
        auto add = [&](const float* s, __half* d, size_t n) {
            ca.src[j] = (const float4*)s; ca.dst[j] = (__half2*)d;
            e += (int)(n / 4); ca.end[j] = e; ++j;
        };
        add(x,       xh,    (size_t)B_ * IN_);
        add(hidden,  hidh,  (size_t)L_ * B_ * H_);
        add(i2d_w,   i2dwh, (size_t)H_ * IN_);
        add(w_ih,    wihh,  (size_t)L_ * lw);
        add(w_hh,    whhh,  (size_t)L_ * lw);
        add(mu_w,    headwh,                       (size_t)NH * H_);
        add(sigma_w, headwh + (size_t)NH * H_,     (size_t)NH * H_);
        add(pi_w,    headwh + (size_t)2 * NH * H_, (size_t)NH * H_);
        launch_pdl(conv_kernel, dim3((e + 255) / 256), dim3(256), 0, ca);
    }

    // ---- 2) i2d: h1 = relu(x @ i2d_w^T + b) -> half ----
    {
        GemmP p;
        p.s[0] = { xh, i2dwh, i2d_b, i2d_b, i2d_b, nullptr, h1h, 1 };
        p.s[1] = p.s[0]; p.s[2] = p.s[0];
        p.xTiles = H_ / BN; p.N = H_; p.K = IN_; p.segN = H_;
        launch_pdl(gemm_f16, dim3(p.xTiles, B_ / BM), dim3(256), SMEM_BYTES, p);
    }

    // ---- 3) BIG fused GEMM: gh0 | gi0 | gh1 ----
    {
        GemmP p;
        p.s[0] = { hidh,      whhh,      b_hh,      b_hh,      b_hh,      nullptr, ghh0, 0 };
        p.s[1] = { h1h,       wihh,      b_ih,      b_ih,      b_ih,      nullptr, gih0, 0 };
        p.s[2] = { hidh + lh, whhh + lw, b_hh + lb, b_hh + lb, b_hh + lb, nullptr, ghh1, 0 };
        p.xTiles = 3 * H_ / BN; p.N = 3 * H_; p.K = H_; p.segN = 3 * H_;
        launch_pdl(gemm_f16, dim3(3 * p.xTiles, B_ / BM), dim3(256), SMEM_BYTES, p);
    }

    // ---- 4) gate 0 ----
    launch_pdl(gru_gate_kernel, dim3(gateGrid), dim3(256), 0,
               (const __half2*)gih0, (const __half2*)ghh0,
               (const float4*)hidden,
               (float4*)out_hidden, (__half2*)h2h, (__half2*)nullptr);

    // ---- 5) gi1 GEMM (A = h2h from gate0) ----
    {
        GemmP p;
        p.s[0] = { h2h, wihh + lw, b_ih + lb, b_ih + lb, b_ih + lb, nullptr, gih1, 0 };
        p.s[1] = p.s[0]; p.s[2] = p.s[0];
        p.xTiles = 3 * H_ / BN; p.N = 3 * H_; p.K = H_; p.segN = 3 * H_;
        launch_pdl(gemm_f16, dim3(p.xTiles, B_ / BM), dim3(256), SMEM_BYTES, p);
    }

    // ---- 6) gate 1 ----
    launch_pdl(gru_gate_kernel, dim3(gateGrid), dim3(256), 0,
               (const __half2*)gih1, (const __half2*)ghh1,
               (const float4*)(hidden + lh),
               (float4*)(out_hidden + lh), (__half2*)nullptr, (__half2*)houth);

    // ---- 7) MDN heads: one fused GEMM (mu | sigma | pi), N = 2304 ----
    {
        GemmP p;
        p.s[0] = { houth, headwh, mu_b, sigma_b, pi_b, out, nullptr, 2 };
        p.s[1] = p.s[0]; p.s[2] = p.s[0];
        p.xTiles = NHEADS3 / BN; p.N = NHEADS3; p.K = H_; p.segN = NH;
        launch_pdl(gemm_f16, dim3(p.xTiles, B_ / BM), dim3(256), SMEM_BYTES, p);
    }

    // ---- 8) pi softmax ----
    launch_pdl(pi_softmax_kernel, dim3(smGrid), dim3(256), 0, out_pi);
}